// round 8
// baseline (speedup 1.0000x reference)
#include <cuda_runtime.h>
#include <cstdint>

#define SEQ 16384
#define EMB 50
#define HID 300
#define G4  1200
#define NT  20
#define TAG_START 18
#define TAG_STOP  19
#define NEGV -10000.0f
#define NCHUNK 128
#define CHL    128

// ---------------- scratch (static device globals; no allocations) ----------
__device__ float g_xg[2][SEQ][G4];                 // input projections, both dirs
__device__ __align__(16) float g_lstm[SEQ][2*HID]; // [hf | hb] per t
__device__ __align__(16) float g_feats[SEQ][NT];
__device__ unsigned char g_bps[SEQ][NT];
__device__ unsigned char g_exit[NCHUNK][NT];
__device__ int g_top[NCHUNK];
__device__ int g_best;

// ---------------- K1: xg = emb @ w_ih^T + b_ih + b_hh (both directions) ----
__global__ void xg_kernel(const int* __restrict__ sentence, const float* __restrict__ embed,
                          const float* __restrict__ w_ih_f, const float* __restrict__ b_ih_f,
                          const float* __restrict__ b_hh_f,
                          const float* __restrict__ w_ih_b, const float* __restrict__ b_ih_b,
                          const float* __restrict__ b_hh_b)
{
    const int TB = 16;
    int dir = blockIdx.y;
    int tq  = blockIdx.x;
    __shared__ float es[TB][EMB];
    const float* w_ih = dir ? w_ih_b : w_ih_f;
    const float* bi   = dir ? b_ih_b : b_ih_f;
    const float* bh   = dir ? b_hh_b : b_hh_f;
    int tid = threadIdx.x;

    for (int i = tid; i < TB * EMB; i += blockDim.x) {
        int tl = i / EMB, k = i - tl * EMB;
        int t  = tq * TB + tl;
        int st = dir ? (SEQ - 1 - t) : t;
        es[tl][k] = embed[(long)sentence[st] * EMB + k];
    }
    __syncthreads();

    if (tid < HID) {
        for (int gate = 0; gate < 4; gate++) {
            int row = gate * HID + tid;
            float w[EMB];
            #pragma unroll
            for (int k = 0; k < EMB; k++) w[k] = w_ih[row * EMB + k];
            float b = bi[row] + bh[row];
            for (int tl = 0; tl < TB; tl++) {
                float acc = b;
                #pragma unroll
                for (int k = 0; k < EMB; k++) acc = fmaf(w[k], es[tl][k], acc);
                g_xg[dir][tq * TB + tl][row] = acc;
            }
        }
    }
}

// ---------------- K2: the sequential LSTM, one 8-CTA cluster per direction --
// SMEM: weights 152*300 fp32, h double-buffer 2*304, gates 152, c-state 40.
#define LTH 608
#define SMEM_W 45600
#define SMEM_FLOATS (SMEM_W + 2*304 + 152 + 40)
#define SMEM_BYTES  (SMEM_FLOATS * 4)

__device__ __forceinline__ unsigned smem_u32(const void* p) {
    return (unsigned)__cvta_generic_to_shared(p);
}

__global__ void __cluster_dims__(8,1,1) __launch_bounds__(LTH, 1)
lstm_kernel(const float* __restrict__ w_hh_f, const float* __restrict__ w_hh_b,
            const float* __restrict__ h0, const float* __restrict__ c0)
{
    extern __shared__ float sm[];
    float* w_s  = sm;               // [NR][300], NR <= 152
    float* hbuf = sm + SMEM_W;      // [2][304]
    float* gsh  = hbuf + 2*304;     // [152]
    float* cst  = gsh + 152;        // [40]

    int tid  = threadIdx.x;
    int rank = blockIdx.x & 7;
    int dir  = blockIdx.x >> 3;
    int nj   = (rank < 4) ? 38 : 37;
    int j0   = (rank < 4) ? rank * 38 : 152 + (rank - 4) * 37;
    int NR   = 4 * nj;
    const float* w_hh = dir ? w_hh_b : w_hh_f;

    // Load weight slice into SMEM: local row r = gate*nj + jj -> global row gate*300 + j0 + jj
    for (int i = tid; i < NR * 300; i += LTH) {
        int r = i / 300, c = i - r * 300;
        int gate = r / nj, jj = r - gate * nj;
        w_s[i] = w_hh[(gate * HID + j0 + jj) * HID + c];
    }
    for (int i = tid; i < HID; i += LTH) hbuf[i] = h0[dir * HID + i];
    if (tid < nj) cst[tid] = c0[dir * HID + j0 + tid];
    __syncthreads();
    asm volatile("barrier.cluster.arrive.aligned;" ::: "memory");
    asm volatile("barrier.cluster.wait.aligned;"   ::: "memory");

    // static matvec mapping: item = tid -> (row r, col-segment s); cols s+4k, k<75
    int r = tid >> 2, s = tid & 3;
    bool mv = (r < NR);
    int gate = mv ? (r / nj) : 0;
    int jj   = mv ? (r - gate * nj) : 0;
    int xcol = gate * HID + j0 + jj;
    const float* xg_base = &g_xg[dir][0][xcol];
    const float* wrow = w_s + r * 300 + s;

    unsigned ha0 = 0, ha1 = 0;
    if (tid < nj) {
        ha0 = smem_u32(&hbuf[0 * 304 + j0 + tid]);
        ha1 = smem_u32(&hbuf[1 * 304 + j0 + tid]);
    }

    #pragma unroll 1
    for (int t = 0; t < SEQ; t++) {
        int cur = t & 1;
        float xv = 0.f;
        if (mv && s == 0) xv = xg_base[(long)t * G4];   // LDG hidden under matvec

        float acc = 0.f;
        const float* hp = hbuf + cur * 304 + s;
        if (mv) {
            #pragma unroll
            for (int k = 0; k < 75; k++) acc = fmaf(wrow[4 * k], hp[4 * k], acc);
        }
        acc += __shfl_xor_sync(0xffffffffu, acc, 1);
        acc += __shfl_xor_sync(0xffffffffu, acc, 2);
        if (mv && s == 0) gsh[r] = acc + xv;
        __syncthreads();

        if (tid < nj) {
            float gi = gsh[tid];
            float gf = gsh[nj + tid];
            float gg = gsh[2 * nj + tid];
            float go = gsh[3 * nj + tid];
            float ig = 1.f / (1.f + expf(-gi));
            float fg = 1.f / (1.f + expf(-gf));
            float cc = fg * cst[tid] + ig * tanhf(gg);
            cst[tid] = cc;
            float h = (1.f / (1.f + expf(-go))) * tanhf(cc);

            int outt = dir ? (SEQ - 1 - t) : t;
            g_lstm[outt][dir * HID + j0 + tid] = h;

            unsigned la = cur ? ha0 : ha1;   // write into the "next" buffer
            #pragma unroll
            for (int rk = 0; rk < 8; rk++) {
                unsigned ra;
                asm volatile("mapa.shared::cluster.u32 %0, %1, %2;" : "=r"(ra) : "r"(la), "r"(rk));
                asm volatile("st.shared::cluster.f32 [%0], %1;" :: "r"(ra), "f"(h));
            }
        }
        // release prior DSMEM stores, acquire peers' h for next step
        asm volatile("barrier.cluster.arrive.aligned;" ::: "memory");
        asm volatile("barrier.cluster.wait.aligned;"   ::: "memory");
    }
}

// ---------------- K3: feats = lstm_out @ w_tag^T + b_tag ------------------
__global__ void feats_kernel(const float* __restrict__ w_tag, const float* __restrict__ b_tag)
{
    int idx = blockIdx.x * blockDim.x + threadIdx.x;
    if (idx >= SEQ * NT) return;
    int t = idx / NT, j = idx - t * NT;
    const float4* x4 = reinterpret_cast<const float4*>(g_lstm[t]);
    const float4* w4 = reinterpret_cast<const float4*>(w_tag + j * 2 * HID);
    float acc = b_tag[j];
    #pragma unroll 5
    for (int k = 0; k < 150; k++) {
        float4 a = x4[k], b = w4[k];
        acc += a.x * b.x + a.y * b.y + a.z * b.z + a.w * b.w;
    }
    g_feats[t][j] = acc;
}

// ---------------- K4: sequential Viterbi forward (1 warp) -----------------
__global__ void viterbi_kernel(const float* __restrict__ trans, float* out, int out_size)
{
    int lane = threadIdx.x;
    bool act = lane < NT;
    float tr[NT];
    #pragma unroll
    for (int p = 0; p < NT; p++) tr[p] = act ? trans[lane * NT + p] : NEGV;
    float trstop = act ? trans[TAG_STOP * NT + lane] : NEGV;
    float fv = (lane == TAG_START) ? 0.f : NEGV;

    const int PF = 8;
    float fbuf[PF];
    #pragma unroll
    for (int u = 0; u < PF; u++) fbuf[u] = act ? g_feats[u][lane] : 0.f;

    for (int t0 = 0; t0 < SEQ; t0 += PF) {
        #pragma unroll
        for (int u = 0; u < PF; u++) {
            int t = t0 + u;
            float v[NT]; int id[NT];
            #pragma unroll
            for (int p = 0; p < NT; p++) {
                v[p] = __shfl_sync(0xffffffffu, fv, p) + tr[p];
                id[p] = p;
            }
            // static tree argmax; strict '>' => first-max wins (matches jnp.argmax)
            #define CMB(a,b) { if (v[b] > v[a]) { v[a] = v[b]; id[a] = id[b]; } }
            CMB(0,1) CMB(2,3) CMB(4,5) CMB(6,7) CMB(8,9)
            CMB(10,11) CMB(12,13) CMB(14,15) CMB(16,17) CMB(18,19)
            CMB(0,2) CMB(4,6) CMB(8,10) CMB(12,14) CMB(16,18)
            CMB(0,4) CMB(8,12)
            CMB(0,8)
            CMB(0,16)
            #undef CMB
            if (act) g_bps[t][lane] = (unsigned char)id[0];
            fv = v[0] + fbuf[u];
            int tn = t + PF;
            fbuf[u] = (act && tn < SEQ) ? g_feats[tn][lane] : 0.f;
        }
    }

    float bv = act ? (fv + trstop) : NEGV;
    int bi = lane;
    #pragma unroll
    for (int off = 16; off > 0; off >>= 1) {
        float ov = __shfl_down_sync(0xffffffffu, bv, off);
        int   oi = __shfl_down_sync(0xffffffffu, bi, off);
        if (ov > bv || (ov == bv && oi < bi)) { bv = ov; bi = oi; }
    }
    if (lane == 0) {
        g_best = bi;
        if (out_size > 0) out[0] = bv;
    }
}

// ---------------- K5..K7: parallel chunked backtracking --------------------
__global__ void chunkmap_kernel()
{
    int c = blockIdx.x, lane = threadIdx.x;
    if (lane >= NT) return;
    int e = lane;
    int base = c * CHL;
    for (int t = base + CHL - 1; t >= base; t--) e = g_bps[t][e];
    g_exit[c][lane] = (unsigned char)e;
}

__global__ void compose_kernel()
{
    if (threadIdx.x == 0) {
        int e = g_best;
        for (int c = NCHUNK - 1; c >= 0; c--) { g_top[c] = e; e = g_exit[c][e]; }
    }
}

__global__ void replay_kernel(float* out, int out_size)
{
    int c = blockIdx.x;
    if (threadIdx.x != 0) return;
    int e = g_top[c];
    int base = c * CHL;
    for (int t = base + CHL - 1; t >= base; t--) {
        if (1 + t < out_size) out[1 + t] = (float)e;
        e = g_bps[t][e];
    }
}

// ---------------- launch ----------------------------------------------------
extern "C" void kernel_launch(void* const* d_in, const int* in_sizes, int n_in,
                              void* d_out, int out_size)
{
    const int*   sentence = (const int*)  d_in[0];
    const float* embed    = (const float*)d_in[1];
    const float* w_ih_f   = (const float*)d_in[2];
    const float* w_hh_f   = (const float*)d_in[3];
    const float* b_ih_f   = (const float*)d_in[4];
    const float* b_hh_f   = (const float*)d_in[5];
    const float* w_ih_b   = (const float*)d_in[6];
    const float* w_hh_b   = (const float*)d_in[7];
    const float* b_ih_b   = (const float*)d_in[8];
    const float* b_hh_b   = (const float*)d_in[9];
    const float* h0       = (const float*)d_in[10];
    const float* c0       = (const float*)d_in[11];
    const float* w_tag    = (const float*)d_in[12];
    const float* b_tag    = (const float*)d_in[13];
    const float* trans    = (const float*)d_in[14];
    float* out = (float*)d_out;

    cudaFuncSetAttribute(lstm_kernel, cudaFuncAttributeMaxDynamicSharedMemorySize, SMEM_BYTES);

    xg_kernel<<<dim3(SEQ / 16, 2), 320>>>(sentence, embed,
                                          w_ih_f, b_ih_f, b_hh_f,
                                          w_ih_b, b_ih_b, b_hh_b);
    lstm_kernel<<<16, LTH, SMEM_BYTES>>>(w_hh_f, w_hh_b, h0, c0);
    feats_kernel<<<(SEQ * NT + 255) / 256, 256>>>(w_tag, b_tag);
    viterbi_kernel<<<1, 32>>>(trans, out, out_size);
    chunkmap_kernel<<<NCHUNK, 32>>>();
    compose_kernel<<<1, 32>>>();
    replay_kernel<<<NCHUNK, 32>>>(out, out_size);
}

// round 11
// speedup vs baseline: 1.0866x; 1.0866x over previous
#include <cuda_runtime.h>
#include <cstdint>

#define SEQ 16384
#define EMB 50
#define HID 300
#define G4  1200
#define NT  20
#define TAG_START 18
#define TAG_STOP  19
#define NEGV -10000.0f
#define NCHUNK 128
#define CHL    128

// ---------------- scratch (static device globals; no allocations) ----------
__device__ float g_xg[2][SEQ][G4];                 // input projections, both dirs
__device__ __align__(16) float g_lstm[SEQ][2*HID]; // [hf | hb] per t
__device__ __align__(16) float g_feats[SEQ][NT];
__device__ unsigned char g_bps[SEQ][NT];
__device__ unsigned char g_exit[NCHUNK][NT];
__device__ int g_top[NCHUNK];
__device__ int g_best;

// ---------------- K1: xg = emb @ w_ih^T + b_ih + b_hh (both directions) ----
__global__ void xg_kernel(const int* __restrict__ sentence, const float* __restrict__ embed,
                          const float* __restrict__ w_ih_f, const float* __restrict__ b_ih_f,
                          const float* __restrict__ b_hh_f,
                          const float* __restrict__ w_ih_b, const float* __restrict__ b_ih_b,
                          const float* __restrict__ b_hh_b)
{
    const int TB = 16;
    int dir = blockIdx.y;
    int tq  = blockIdx.x;
    __shared__ float es[TB][EMB];
    const float* w_ih = dir ? w_ih_b : w_ih_f;
    const float* bi   = dir ? b_ih_b : b_ih_f;
    const float* bh   = dir ? b_hh_b : b_hh_f;
    int tid = threadIdx.x;

    for (int i = tid; i < TB * EMB; i += blockDim.x) {
        int tl = i / EMB, k = i - tl * EMB;
        int t  = tq * TB + tl;
        int st = dir ? (SEQ - 1 - t) : t;
        es[tl][k] = embed[(long)sentence[st] * EMB + k];
    }
    __syncthreads();

    if (tid < HID) {
        for (int gate = 0; gate < 4; gate++) {
            int row = gate * HID + tid;
            float w[EMB];
            #pragma unroll
            for (int k = 0; k < EMB; k++) w[k] = w_ih[row * EMB + k];
            float b = bi[row] + bh[row];
            for (int tl = 0; tl < TB; tl++) {
                float acc = b;
                #pragma unroll
                for (int k = 0; k < EMB; k++) acc = fmaf(w[k], es[tl][k], acc);
                g_xg[dir][tq * TB + tl][row] = acc;
            }
        }
    }
}

// ---------------- K2: sequential LSTM, 8-CTA cluster per direction ---------
// Weights live in REGISTERS as packed f32x2 pairs; matvec uses fma.rn.f32x2.
// 320 threads: r = tid>>1 (row, up to 152), s = tid&1 (column segment).
// Segment s=0: cols [0,152), s=1: cols [152,300) (zero-padded to 152 pairs).
#define LTH 320

__device__ __forceinline__ unsigned smem_u32(const void* p) {
    return (unsigned)__cvta_generic_to_shared(p);
}

__global__ void __cluster_dims__(8,1,1) __launch_bounds__(LTH, 1)
lstm_kernel(const float* __restrict__ w_hh_f, const float* __restrict__ w_hh_b,
            const float* __restrict__ h0, const float* __restrict__ c0)
{
    __shared__ float hbuf[2][304];   // double-buffered full h (pads zeroed)
    __shared__ float gsh[152];       // gate pre-activations for this CTA

    int tid  = threadIdx.x;
    int rank = blockIdx.x & 7;
    int dir  = blockIdx.x >> 3;
    int nj   = (rank < 4) ? 38 : 37;
    int j0   = (rank < 4) ? rank * 38 : 152 + (rank - 4) * 37;
    int NR   = 4 * nj;
    const float* w_hh = dir ? w_hh_b : w_hh_f;

    int r = tid >> 1, s = tid & 1;
    bool mv = (r < NR);
    int gate = mv ? (r / nj) : 0;
    int jj   = mv ? (r - gate * nj) : 0;
    int grow = gate * HID + j0 + jj;        // global gate row / xg column
    int off  = s ? 152 : 0;
    int ncol = s ? 148 : 152;

    // --- weights -> registers, packed as f32x2 pairs, zero-padded ---
    unsigned long long wreg[76];
    {
        const float* wsrc = w_hh + (long)grow * HID + off;
        #pragma unroll
        for (int i = 0; i < 76; i++) {
            float a = 0.f, b = 0.f;
            if (mv && 2*i     < ncol) a = wsrc[2*i];
            if (mv && 2*i + 1 < ncol) b = wsrc[2*i+1];
            asm("mov.b64 %0, {%1, %2};" : "=l"(wreg[i])
                : "r"(__float_as_uint(a)), "r"(__float_as_uint(b)));
        }
    }

    // --- init h buffers (values + zero pads) and c-state (register) ---
    for (int i = tid; i < 2*304; i += LTH) {
        int c = i & 0x1FF; c = i - (i/304)*304;
        hbuf[i/304][c] = (c < HID) ? h0[dir*HID + c] : 0.f;
    }
    float cc = (tid < nj) ? c0[dir*HID + j0 + tid] : 0.f;
    __syncthreads();
    asm volatile("barrier.cluster.arrive.aligned;" ::: "memory");
    asm volatile("barrier.cluster.wait.aligned;"   ::: "memory");

    unsigned hb0 = smem_u32(&hbuf[0][off]);
    unsigned hb1 = smem_u32(&hbuf[1][off]);
    unsigned ha0 = 0, ha1 = 0;
    if (tid < nj) {
        ha0 = smem_u32(&hbuf[0][j0 + tid]);
        ha1 = smem_u32(&hbuf[1][j0 + tid]);
    }

    const float* xg_base = &g_xg[dir][0][grow];
    float xv_next = mv ? xg_base[0] : 0.f;   // prefetch t=0

    #pragma unroll 1
    for (int t = 0; t < SEQ; t++) {
        int cur = t & 1;
        float xv = xv_next;
        if (mv) {
            long tn = (t + 1 < SEQ) ? (long)(t + 1) : (long)t;
            xv_next = xg_base[tn * G4];      // prefetch next step's x-gate
        }

        unsigned hbase = cur ? hb1 : hb0;
        unsigned long long a0 = 0, a1 = 0, a2 = 0, a3 = 0;
        #pragma unroll
        for (int k = 0; k < 38; k++) {
            unsigned long long p0, p1;
            asm volatile("{\n\t"
                ".reg .b32 x,y,z,w;\n\t"
                "ld.shared.v4.b32 {x,y,z,w}, [%2];\n\t"
                "mov.b64 %0, {x,y};\n\t"
                "mov.b64 %1, {z,w};\n\t"
                "}" : "=l"(p0), "=l"(p1) : "r"(hbase + 16u*k));
            if (k & 1) {
                asm("fma.rn.f32x2 %0, %1, %2, %0;" : "+l"(a2) : "l"(wreg[2*k]),   "l"(p0));
                asm("fma.rn.f32x2 %0, %1, %2, %0;" : "+l"(a3) : "l"(wreg[2*k+1]), "l"(p1));
            } else {
                asm("fma.rn.f32x2 %0, %1, %2, %0;" : "+l"(a0) : "l"(wreg[2*k]),   "l"(p0));
                asm("fma.rn.f32x2 %0, %1, %2, %0;" : "+l"(a1) : "l"(wreg[2*k+1]), "l"(p1));
            }
        }
        asm("add.rn.f32x2 %0, %0, %1;" : "+l"(a0) : "l"(a1));
        asm("add.rn.f32x2 %0, %0, %1;" : "+l"(a2) : "l"(a3));
        asm("add.rn.f32x2 %0, %0, %1;" : "+l"(a0) : "l"(a2));
        unsigned ulo, uhi;
        asm("mov.b64 {%0, %1}, %2;" : "=r"(ulo), "=r"(uhi) : "l"(a0));
        float acc = __uint_as_float(ulo) + __uint_as_float(uhi);

        acc += __shfl_xor_sync(0xffffffffu, acc, 1);   // combine the 2 segments
        if (mv && s == 0) gsh[r] = acc + xv;
        __syncthreads();

        if (tid < nj) {
            float gi = gsh[tid];
            float gf = gsh[nj + tid];
            float gg = gsh[2 * nj + tid];
            float go = gsh[3 * nj + tid];
            float ig = 1.f / (1.f + expf(-gi));
            float fg = 1.f / (1.f + expf(-gf));
            cc = fg * cc + ig * tanhf(gg);
            float h = (1.f / (1.f + expf(-go))) * tanhf(cc);

            int outt = dir ? (SEQ - 1 - t) : t;
            g_lstm[outt][dir * HID + j0 + tid] = h;

            unsigned la = cur ? ha0 : ha1;   // write into the "next" buffer
            #pragma unroll
            for (int rk = 0; rk < 8; rk++) {
                unsigned ra;
                asm volatile("mapa.shared::cluster.u32 %0, %1, %2;" : "=r"(ra) : "r"(la), "r"(rk));
                asm volatile("st.shared::cluster.f32 [%0], %1;" :: "r"(ra), "f"(h));
            }
        }
        asm volatile("barrier.cluster.arrive.aligned;" ::: "memory");
        asm volatile("barrier.cluster.wait.aligned;"   ::: "memory");
    }
}

// ---------------- K3: feats = lstm_out @ w_tag^T + b_tag ------------------
__global__ void feats_kernel(const float* __restrict__ w_tag, const float* __restrict__ b_tag)
{
    int idx = blockIdx.x * blockDim.x + threadIdx.x;
    if (idx >= SEQ * NT) return;
    int t = idx / NT, j = idx - t * NT;
    const float4* x4 = reinterpret_cast<const float4*>(g_lstm[t]);
    const float4* w4 = reinterpret_cast<const float4*>(w_tag + j * 2 * HID);
    float acc = b_tag[j];
    #pragma unroll 5
    for (int k = 0; k < 150; k++) {
        float4 a = x4[k], b = w4[k];
        acc += a.x * b.x + a.y * b.y + a.z * b.z + a.w * b.w;
    }
    g_feats[t][j] = acc;
}

// ---------------- K4: sequential Viterbi forward (1 warp) -----------------
__global__ void viterbi_kernel(const float* __restrict__ trans, float* out, int out_size)
{
    int lane = threadIdx.x;
    bool act = lane < NT;
    float tr[NT];
    #pragma unroll
    for (int p = 0; p < NT; p++) tr[p] = act ? trans[lane * NT + p] : NEGV;
    float trstop = act ? trans[TAG_STOP * NT + lane] : NEGV;
    float fv = (lane == TAG_START) ? 0.f : NEGV;

    const int PF = 8;
    float fbuf[PF];
    #pragma unroll
    for (int u = 0; u < PF; u++) fbuf[u] = act ? g_feats[u][lane] : 0.f;

    for (int t0 = 0; t0 < SEQ; t0 += PF) {
        #pragma unroll
        for (int u = 0; u < PF; u++) {
            int t = t0 + u;
            float v[NT]; int id[NT];
            #pragma unroll
            for (int p = 0; p < NT; p++) {
                v[p] = __shfl_sync(0xffffffffu, fv, p) + tr[p];
                id[p] = p;
            }
            #define CMB(a,b) { if (v[b] > v[a]) { v[a] = v[b]; id[a] = id[b]; } }
            CMB(0,1) CMB(2,3) CMB(4,5) CMB(6,7) CMB(8,9)
            CMB(10,11) CMB(12,13) CMB(14,15) CMB(16,17) CMB(18,19)
            CMB(0,2) CMB(4,6) CMB(8,10) CMB(12,14) CMB(16,18)
            CMB(0,4) CMB(8,12)
            CMB(0,8)
            CMB(0,16)
            #undef CMB
            if (act) g_bps[t][lane] = (unsigned char)id[0];
            fv = v[0] + fbuf[u];
            int tn = t + PF;
            fbuf[u] = (act && tn < SEQ) ? g_feats[tn][lane] : 0.f;
        }
    }

    float bv = act ? (fv + trstop) : NEGV;
    int bi = lane;
    #pragma unroll
    for (int off = 16; off > 0; off >>= 1) {
        float ov = __shfl_down_sync(0xffffffffu, bv, off);
        int   oi = __shfl_down_sync(0xffffffffu, bi, off);
        if (ov > bv || (ov == bv && oi < bi)) { bv = ov; bi = oi; }
    }
    if (lane == 0) {
        g_best = bi;
        if (out_size > 0) out[0] = bv;
    }
}

// ---------------- K5..K7: parallel chunked backtracking --------------------
__global__ void chunkmap_kernel()
{
    int c = blockIdx.x, lane = threadIdx.x;
    if (lane >= NT) return;
    int e = lane;
    int base = c * CHL;
    for (int t = base + CHL - 1; t >= base; t--) e = g_bps[t][e];
    g_exit[c][lane] = (unsigned char)e;
}

__global__ void compose_kernel()
{
    if (threadIdx.x == 0) {
        int e = g_best;
        for (int c = NCHUNK - 1; c >= 0; c--) { g_top[c] = e; e = g_exit[c][e]; }
    }
}

__global__ void replay_kernel(float* out, int out_size)
{
    int c = blockIdx.x;
    if (threadIdx.x != 0) return;
    int e = g_top[c];
    int base = c * CHL;
    for (int t = base + CHL - 1; t >= base; t--) {
        if (1 + t < out_size) out[1 + t] = (float)e;
        e = g_bps[t][e];
    }
}

// ---------------- launch ----------------------------------------------------
extern "C" void kernel_launch(void* const* d_in, const int* in_sizes, int n_in,
                              void* d_out, int out_size)
{
    const int*   sentence = (const int*)  d_in[0];
    const float* embed    = (const float*)d_in[1];
    const float* w_ih_f   = (const float*)d_in[2];
    const float* w_hh_f   = (const float*)d_in[3];
    const float* b_ih_f   = (const float*)d_in[4];
    const float* b_hh_f   = (const float*)d_in[5];
    const float* w_ih_b   = (const float*)d_in[6];
    const float* w_hh_b   = (const float*)d_in[7];
    const float* b_ih_b   = (const float*)d_in[8];
    const float* b_hh_b   = (const float*)d_in[9];
    const float* h0       = (const float*)d_in[10];
    const float* c0       = (const float*)d_in[11];
    const float* w_tag    = (const float*)d_in[12];
    const float* b_tag    = (const float*)d_in[13];
    const float* trans    = (const float*)d_in[14];
    float* out = (float*)d_out;

    xg_kernel<<<dim3(SEQ / 16, 2), 320>>>(sentence, embed,
                                          w_ih_f, b_ih_f, b_hh_f,
                                          w_ih_b, b_ih_b, b_hh_b);
    lstm_kernel<<<16, LTH>>>(w_hh_f, w_hh_b, h0, c0);
    feats_kernel<<<(SEQ * NT + 255) / 256, 256>>>(w_tag, b_tag);
    viterbi_kernel<<<1, 32>>>(trans, out, out_size);
    chunkmap_kernel<<<NCHUNK, 32>>>();
    compose_kernel<<<1, 32>>>();
    replay_kernel<<<NCHUNK, 32>>>(out, out_size);
}

// round 12
// speedup vs baseline: 1.7126x; 1.5761x over previous
#include <cuda_runtime.h>
#include <cstdint>

#define SEQ 16384
#define EMB 50
#define HID 300
#define G4  1200
#define NT  20
#define TAG_START 18
#define TAG_STOP  19
#define NEGV -10000.0f
#define NCHUNK 128
#define CHL    128

// ---------------- scratch (static device globals; no allocations) ----------
__device__ float g_xg[2][SEQ][G4];                 // input projections, both dirs
__device__ __align__(16) float g_lstm[SEQ][2*HID]; // [hf | hb] per t
__device__ __align__(16) float g_feats[SEQ][NT];
__device__ unsigned char g_bps[SEQ][NT];
__device__ unsigned char g_exit[NCHUNK][NT];
__device__ int g_top[NCHUNK];
__device__ int g_best;

// ---------------- K1: xg = emb @ w_ih^T + b_ih + b_hh (both directions) ----
__global__ void xg_kernel(const int* __restrict__ sentence, const float* __restrict__ embed,
                          const float* __restrict__ w_ih_f, const float* __restrict__ b_ih_f,
                          const float* __restrict__ b_hh_f,
                          const float* __restrict__ w_ih_b, const float* __restrict__ b_ih_b,
                          const float* __restrict__ b_hh_b)
{
    const int TB = 16;
    int dir = blockIdx.y;
    int tq  = blockIdx.x;
    __shared__ float es[TB][EMB];
    const float* w_ih = dir ? w_ih_b : w_ih_f;
    const float* bi   = dir ? b_ih_b : b_ih_f;
    const float* bh   = dir ? b_hh_b : b_hh_f;
    int tid = threadIdx.x;

    for (int i = tid; i < TB * EMB; i += blockDim.x) {
        int tl = i / EMB, k = i - tl * EMB;
        int t  = tq * TB + tl;
        int st = dir ? (SEQ - 1 - t) : t;
        es[tl][k] = embed[(long)sentence[st] * EMB + k];
    }
    __syncthreads();

    if (tid < HID) {
        for (int gate = 0; gate < 4; gate++) {
            int row = gate * HID + tid;
            float w[EMB];
            #pragma unroll
            for (int k = 0; k < EMB; k++) w[k] = w_ih[row * EMB + k];
            float b = bi[row] + bh[row];
            for (int tl = 0; tl < TB; tl++) {
                float acc = b;
                #pragma unroll
                for (int k = 0; k < EMB; k++) acc = fmaf(w[k], es[tl][k], acc);
                g_xg[dir][tq * TB + tl][row] = acc;
            }
        }
    }
}

// ---------------- K2: sequential LSTM, 8-CTA cluster per direction ---------
// Weights in registers (fma.rn.f32x2); inter-CTA h exchange via st.async +
// ping-pong mbarriers (NO per-step cluster barrier).
#define LTH 320

__device__ __forceinline__ unsigned smem_u32(const void* p) {
    return (unsigned)__cvta_generic_to_shared(p);
}

__device__ __forceinline__ void mbar_wait_acq(unsigned mbar, unsigned parity) {
    asm volatile(
        "{\n\t"
        ".reg .pred P;\n\t"
        "WL_%=:\n\t"
        "mbarrier.try_wait.parity.acquire.cta.shared::cta.b64 P, [%0], %1, 0x989680;\n\t"
        "@P bra WD_%=;\n\t"
        "bra WL_%=;\n\t"
        "WD_%=:\n\t"
        "}"
        :: "r"(mbar), "r"(parity) : "memory");
}

__global__ void __cluster_dims__(8,1,1) __launch_bounds__(LTH, 1)
lstm_kernel(const float* __restrict__ w_hh_f, const float* __restrict__ w_hh_b,
            const float* __restrict__ h0, const float* __restrict__ c0)
{
    __shared__ float hbuf[2][304];                      // double-buffered full h
    __shared__ float gsh[152];                          // activated gates for this CTA
    __shared__ __align__(8) unsigned long long mbars[2];

    int tid  = threadIdx.x;
    int rank = blockIdx.x & 7;
    int dir  = blockIdx.x >> 3;
    int nj   = (rank < 4) ? 38 : 37;
    int j0   = (rank < 4) ? rank * 38 : 152 + (rank - 4) * 37;
    int NR   = 4 * nj;
    const float* w_hh = dir ? w_hh_b : w_hh_f;

    int r = tid >> 1, s = tid & 1;
    bool mv = (r < NR);
    int gate = mv ? (r / nj) : 0;
    int jj   = mv ? (r - gate * nj) : 0;
    int grow = gate * HID + j0 + jj;        // global gate row / xg column
    int off  = s ? 152 : 0;
    int ncol = s ? 148 : 152;

    // --- weights -> registers, packed as f32x2 pairs, zero-padded ---
    unsigned long long wreg[76];
    {
        const float* wsrc = w_hh + (long)grow * HID + off;
        #pragma unroll
        for (int i = 0; i < 76; i++) {
            float a = 0.f, b = 0.f;
            if (mv && 2*i     < ncol) a = wsrc[2*i];
            if (mv && 2*i + 1 < ncol) b = wsrc[2*i+1];
            asm("mov.b64 %0, {%1, %2};" : "=l"(wreg[i])
                : "r"(__float_as_uint(a)), "r"(__float_as_uint(b)));
        }
    }

    // --- init h buffers (values + zero pads) and c-state (register) ---
    for (int i = tid; i < 2*304; i += LTH) {
        int c = i - (i/304)*304;
        hbuf[i/304][c] = (c < HID) ? h0[dir*HID + c] : 0.f;
    }
    float cc = (tid < nj) ? c0[dir*HID + j0 + tid] : 0.f;

    unsigned mb0 = smem_u32(&mbars[0]);
    unsigned mb1 = smem_u32(&mbars[1]);
    if (tid == 0) {
        asm volatile("mbarrier.init.shared.b64 [%0], %1;" :: "r"(mb0), "r"(1) : "memory");
        asm volatile("mbarrier.init.shared.b64 [%0], %1;" :: "r"(mb1), "r"(1) : "memory");
        // pre-arm both phases: 300 floats = 1200 tx-bytes per step
        asm volatile("mbarrier.arrive.expect_tx.shared.b64 _, [%0], %1;" :: "r"(mb0), "r"(1200) : "memory");
        asm volatile("mbarrier.arrive.expect_tx.shared.b64 _, [%0], %1;" :: "r"(mb1), "r"(1200) : "memory");
    }
    __syncthreads();
    asm volatile("barrier.cluster.arrive.aligned;" ::: "memory");   // one-time: peers' mbarriers live
    asm volatile("barrier.cluster.wait.aligned;"   ::: "memory");

    unsigned hb0 = smem_u32(&hbuf[0][off]);
    unsigned hb1 = smem_u32(&hbuf[1][off]);
    unsigned ha0 = 0, ha1 = 0;
    if (tid < nj) {
        ha0 = smem_u32(&hbuf[0][j0 + tid]);
        ha1 = smem_u32(&hbuf[1][j0 + tid]);
    }

    const float* xg_base = &g_xg[dir][0][grow];
    float xv_next = mv ? xg_base[0] : 0.f;   // prefetch t=0
    int ph0 = 0, ph1 = 0;

    #pragma unroll 1
    for (int t = 0; t < SEQ; t++) {
        int cur = t & 1;

        // wait for all 8 ranks' h-slices for this step (t=0: h0 loaded locally)
        if (t > 0) {
            unsigned mb = cur ? mb1 : mb0;
            mbar_wait_acq(mb, cur ? (unsigned)ph1 : (unsigned)ph0);
            if (cur) ph1 ^= 1; else ph0 ^= 1;
            if (tid == 0)   // re-arm this barrier for its next use (step t+2)
                asm volatile("mbarrier.arrive.expect_tx.shared.b64 _, [%0], %1;"
                             :: "r"(mb), "r"(1200) : "memory");
        }

        float xv = xv_next;
        if (mv) {
            long tn = (t + 1 < SEQ) ? (long)(t + 1) : (long)t;
            xv_next = xg_base[tn * G4];      // prefetch next step's x-gate
        }

        unsigned hbase = cur ? hb1 : hb0;
        unsigned long long a0 = 0, a1 = 0, a2 = 0, a3 = 0;
        #pragma unroll
        for (int k = 0; k < 38; k++) {
            unsigned long long p0, p1;
            asm volatile("{\n\t"
                ".reg .b32 x,y,z,w;\n\t"
                "ld.shared.v4.b32 {x,y,z,w}, [%2];\n\t"
                "mov.b64 %0, {x,y};\n\t"
                "mov.b64 %1, {z,w};\n\t"
                "}" : "=l"(p0), "=l"(p1) : "r"(hbase + 16u*k));
            if (k & 1) {
                asm("fma.rn.f32x2 %0, %1, %2, %0;" : "+l"(a2) : "l"(wreg[2*k]),   "l"(p0));
                asm("fma.rn.f32x2 %0, %1, %2, %0;" : "+l"(a3) : "l"(wreg[2*k+1]), "l"(p1));
            } else {
                asm("fma.rn.f32x2 %0, %1, %2, %0;" : "+l"(a0) : "l"(wreg[2*k]),   "l"(p0));
                asm("fma.rn.f32x2 %0, %1, %2, %0;" : "+l"(a1) : "l"(wreg[2*k+1]), "l"(p1));
            }
        }
        asm("add.rn.f32x2 %0, %0, %1;" : "+l"(a0) : "l"(a1));
        asm("add.rn.f32x2 %0, %0, %1;" : "+l"(a2) : "l"(a3));
        asm("add.rn.f32x2 %0, %0, %1;" : "+l"(a0) : "l"(a2));
        unsigned ulo, uhi;
        asm("mov.b64 {%0, %1}, %2;" : "=r"(ulo), "=r"(uhi) : "l"(a0));
        float acc = __uint_as_float(ulo) + __uint_as_float(uhi);

        acc += __shfl_xor_sync(0xffffffffu, acc, 1);   // combine the 2 segments
        if (mv && s == 0) {
            // apply the nonlinearity HERE (parallel across gates) to shorten
            // the post-sync serial chain
            float pre = acc + xv;
            float act = (gate == 2) ? tanhf(pre) : (1.f / (1.f + expf(-pre)));
            gsh[r] = act;
        }
        __syncthreads();

        if (tid < nj) {
            float ig = gsh[tid];
            float fg = gsh[nj + tid];
            float gg = gsh[2 * nj + tid];
            float og = gsh[3 * nj + tid];
            cc = fg * cc + ig * gg;
            float h = og * tanhf(cc);

            int outt = dir ? (SEQ - 1 - t) : t;
            g_lstm[outt][dir * HID + j0 + tid] = h;

            // push h_{t+1} slice to all 8 ranks: fused store + tx-arrive on the
            // peer's mb[(t+1)&1]
            unsigned la  = cur ? ha0 : ha1;      // slot in hbuf[1-cur]
            unsigned mbn = cur ? mb0 : mb1;      // mb[1-cur]
            #pragma unroll
            for (int rk = 0; rk < 8; rk++) {
                unsigned dst, rb;
                asm volatile("mapa.shared::cluster.u32 %0, %1, %2;" : "=r"(dst) : "r"(la),  "r"(rk));
                asm volatile("mapa.shared::cluster.u32 %0, %1, %2;" : "=r"(rb)  : "r"(mbn), "r"(rk));
                asm volatile("st.async.shared::cluster.mbarrier::complete_tx::bytes.f32 [%0], %1, [%2];"
                             :: "r"(dst), "f"(h), "r"(rb) : "memory");
            }
        }
        // no barrier here: next step's mbarrier wait provides all ordering
    }

    // drain in-flight st.async before any CTA exits
    asm volatile("barrier.cluster.arrive.aligned;" ::: "memory");
    asm volatile("barrier.cluster.wait.aligned;"   ::: "memory");
}

// ---------------- K3: feats = lstm_out @ w_tag^T + b_tag ------------------
__global__ void feats_kernel(const float* __restrict__ w_tag, const float* __restrict__ b_tag)
{
    int idx = blockIdx.x * blockDim.x + threadIdx.x;
    if (idx >= SEQ * NT) return;
    int t = idx / NT, j = idx - t * NT;
    const float4* x4 = reinterpret_cast<const float4*>(g_lstm[t]);
    const float4* w4 = reinterpret_cast<const float4*>(w_tag + j * 2 * HID);
    float acc = b_tag[j];
    #pragma unroll 5
    for (int k = 0; k < 150; k++) {
        float4 a = x4[k], b = w4[k];
        acc += a.x * b.x + a.y * b.y + a.z * b.z + a.w * b.w;
    }
    g_feats[t][j] = acc;
}

// ---------------- K4: sequential Viterbi forward (1 warp) -----------------
__global__ void viterbi_kernel(const float* __restrict__ trans, float* out, int out_size)
{
    int lane = threadIdx.x;
    bool act = lane < NT;
    float tr[NT];
    #pragma unroll
    for (int p = 0; p < NT; p++) tr[p] = act ? trans[lane * NT + p] : NEGV;
    float trstop = act ? trans[TAG_STOP * NT + lane] : NEGV;
    float fv = (lane == TAG_START) ? 0.f : NEGV;

    const int PF = 8;
    float fbuf[PF];
    #pragma unroll
    for (int u = 0; u < PF; u++) fbuf[u] = act ? g_feats[u][lane] : 0.f;

    for (int t0 = 0; t0 < SEQ; t0 += PF) {
        #pragma unroll
        for (int u = 0; u < PF; u++) {
            int t = t0 + u;
            float v[NT]; int id[NT];
            #pragma unroll
            for (int p = 0; p < NT; p++) {
                v[p] = __shfl_sync(0xffffffffu, fv, p) + tr[p];
                id[p] = p;
            }
            #define CMB(a,b) { if (v[b] > v[a]) { v[a] = v[b]; id[a] = id[b]; } }
            CMB(0,1) CMB(2,3) CMB(4,5) CMB(6,7) CMB(8,9)
            CMB(10,11) CMB(12,13) CMB(14,15) CMB(16,17) CMB(18,19)
            CMB(0,2) CMB(4,6) CMB(8,10) CMB(12,14) CMB(16,18)
            CMB(0,4) CMB(8,12)
            CMB(0,8)
            CMB(0,16)
            #undef CMB
            if (act) g_bps[t][lane] = (unsigned char)id[0];
            fv = v[0] + fbuf[u];
            int tn = t + PF;
            fbuf[u] = (act && tn < SEQ) ? g_feats[tn][lane] : 0.f;
        }
    }

    float bv = act ? (fv + trstop) : NEGV;
    int bi = lane;
    #pragma unroll
    for (int off = 16; off > 0; off >>= 1) {
        float ov = __shfl_down_sync(0xffffffffu, bv, off);
        int   oi = __shfl_down_sync(0xffffffffu, bi, off);
        if (ov > bv || (ov == bv && oi < bi)) { bv = ov; bi = oi; }
    }
    if (lane == 0) {
        g_best = bi;
        if (out_size > 0) out[0] = bv;
    }
}

// ---------------- K5..K7: parallel chunked backtracking --------------------
__global__ void chunkmap_kernel()
{
    int c = blockIdx.x, lane = threadIdx.x;
    if (lane >= NT) return;
    int e = lane;
    int base = c * CHL;
    for (int t = base + CHL - 1; t >= base; t--) e = g_bps[t][e];
    g_exit[c][lane] = (unsigned char)e;
}

__global__ void compose_kernel()
{
    if (threadIdx.x == 0) {
        int e = g_best;
        for (int c = NCHUNK - 1; c >= 0; c--) { g_top[c] = e; e = g_exit[c][e]; }
    }
}

__global__ void replay_kernel(float* out, int out_size)
{
    int c = blockIdx.x;
    if (threadIdx.x != 0) return;
    int e = g_top[c];
    int base = c * CHL;
    for (int t = base + CHL - 1; t >= base; t--) {
        if (1 + t < out_size) out[1 + t] = (float)e;
        e = g_bps[t][e];
    }
}

// ---------------- launch ----------------------------------------------------
extern "C" void kernel_launch(void* const* d_in, const int* in_sizes, int n_in,
                              void* d_out, int out_size)
{
    const int*   sentence = (const int*)  d_in[0];
    const float* embed    = (const float*)d_in[1];
    const float* w_ih_f   = (const float*)d_in[2];
    const float* w_hh_f   = (const float*)d_in[3];
    const float* b_ih_f   = (const float*)d_in[4];
    const float* b_hh_f   = (const float*)d_in[5];
    const float* w_ih_b   = (const float*)d_in[6];
    const float* w_hh_b   = (const float*)d_in[7];
    const float* b_ih_b   = (const float*)d_in[8];
    const float* b_hh_b   = (const float*)d_in[9];
    const float* h0       = (const float*)d_in[10];
    const float* c0       = (const float*)d_in[11];
    const float* w_tag    = (const float*)d_in[12];
    const float* b_tag    = (const float*)d_in[13];
    const float* trans    = (const float*)d_in[14];
    float* out = (float*)d_out;

    xg_kernel<<<dim3(SEQ / 16, 2), 320>>>(sentence, embed,
                                          w_ih_f, b_ih_f, b_hh_f,
                                          w_ih_b, b_ih_b, b_hh_b);
    lstm_kernel<<<16, LTH>>>(w_hh_f, w_hh_b, h0, c0);
    feats_kernel<<<(SEQ * NT + 255) / 256, 256>>>(w_tag, b_tag);
    viterbi_kernel<<<1, 32>>>(trans, out, out_size);
    chunkmap_kernel<<<NCHUNK, 32>>>();
    compose_kernel<<<1, 32>>>();
    replay_kernel<<<NCHUNK, 32>>>(out, out_size);
}